// round 7
// baseline (speedup 1.0000x reference)
#include <cuda_runtime.h>
#include <stdint.h>

#define N_TBINS 1024
#define TK 96
#define TR 48

__device__ float g_scaled[N_TBINS];
__device__ uint2 g_ksub[TK];
__device__ uint2 g_rs0[TR];
__device__ uint2 g_rs1[TR];
__device__ int   g_tstop;

__device__ __forceinline__ uint32_t rotl32(uint32_t x, int r) {
    return __funnelshift_l(x, x, r);
}

__device__ __forceinline__ uint2 threefry2x32(uint2 key, uint32_t x0, uint32_t x1) {
    uint32_t ks0 = key.x, ks1 = key.y;
    uint32_t ks2 = ks0 ^ ks1 ^ 0x1BD11BDAu;
    x0 += ks0; x1 += ks1;
#define TF_R(r) { x0 += x1; x1 = rotl32(x1, r); x1 ^= x0; }
    TF_R(13) TF_R(15) TF_R(26) TF_R(6)
    x0 += ks1; x1 += ks2 + 1u;
    TF_R(17) TF_R(29) TF_R(16) TF_R(24)
    x0 += ks2; x1 += ks0 + 2u;
    TF_R(13) TF_R(15) TF_R(26) TF_R(6)
    x0 += ks0; x1 += ks1 + 3u;
    TF_R(17) TF_R(29) TF_R(16) TF_R(24)
    x0 += ks1; x1 += ks2 + 4u;
    TF_R(13) TF_R(15) TF_R(26) TF_R(6)
    x0 += ks2; x1 += ks0 + 5u;
#undef TF_R
    return make_uint2(x0, x1);
}

__device__ __forceinline__ float u01(uint2 key, uint32_t j) {
    uint2 r = threefry2x32(key, 0u, j);
    uint32_t bits = r.x ^ r.y;
    return __uint_as_float((bits >> 9) | 0x3f800000u) - 1.0f;
}

// XLA Lanczos lgamma (g=7), x >= 1 here.
__device__ __forceinline__ float lgamma_xla(float x) {
    float z = __fsub_rn(x, 1.0f);
    float sum = 0.99999999999980993f;
    const float lanc[8] = {
        676.520368121885098567009190444019f,
        -1259.13921672240287047156078755283f,
        771.3234287776530788486528258894f,
        -176.61502916214059906584551354f,
        12.507343278686904814458936853f,
        -0.13857109526572011689554707f,
        9.984369578019570859563e-6f,
        1.50563273514931155834e-7f};
#pragma unroll
    for (int i = 0; i < 8; i++) {
        float denom = __fadd_rn(__fadd_rn(z, (float)i), 1.0f);
        sum = __fadd_rn(sum, __fdiv_rn(lanc[i], denom));
    }
    float t = __fadd_rn(7.5f, z);
    float log_t = __fadd_rn(2.0149030205422647f, log1pf(__fdiv_rn(z, 7.5f)));
    float v = __fmul_rn(__fsub_rn(__fadd_rn(z, 0.5f), __fdiv_rn(t, log_t)), log_t);
    return __fadd_rn(__fadd_rn(0.9189385332046727f, v), logf(sum));
}

// One Hormann rejection iteration: returns accept decision, writes k.
__device__ __forceinline__ bool rej_step(uint2 s0, uint2 s1, uint32_t j,
                                         float lam, float log_lam, float aa,
                                         float bb, float inv_alpha, float v_r,
                                         float& kc_out) {
    float u = __fsub_rn(u01(s0, j), 0.5f);
    float v = u01(s1, j);
    float us = __fsub_rn(0.5f, fabsf(u));
    float kc = floorf(__fadd_rn(
        __fadd_rn(__fmul_rn(__fadd_rn(__fdiv_rn(__fadd_rn(aa, aa), us), bb), u), lam),
        0.43f));
    kc_out = kc;
    bool accept1 = (us >= 0.07f) && (v <= v_r);
    if (accept1) return true;
    bool reject = (kc < 0.0f) || ((us < 0.013f) && (v > us));
    if (reject) return false;
    float s = logf(__fdiv_rn(__fmul_rn(v, inv_alpha),
                             __fadd_rn(__fdiv_rn(aa, __fmul_rn(us, us)), bb)));
    float tt = __fsub_rn(__fadd_rn(-lam, __fmul_rn(kc, log_lam)),
                         lgamma_xla(__fadd_rn(kc, 1.0f)));
    return s <= tt;
}

__global__ void __launch_bounds__(32, 1)
chains_kernel() {
    if (threadIdx.x != 0) return;
    g_tstop = 0;
    uint2 key0 = make_uint2(0u, 42u);
    uint2 r = key0;
#pragma unroll 1
    for (int t = 0; t < TK; t++) {
        g_ksub[t] = threefry2x32(r, 0u, 1u);
        r = threefry2x32(r, 0u, 0u);
    }
    uint2 c = key0;
#pragma unroll 1
    for (int t = 0; t < TR; t++) {
        g_rs0[t] = threefry2x32(c, 0u, 1u);
        g_rs1[t] = threefry2x32(c, 0u, 2u);
        c = threefry2x32(c, 0u, 0u);
    }
}

__global__ void __launch_bounds__(256, 1)
setup_kernel(const float* __restrict__ ill,
             const float* __restrict__ pc,
             const float* __restrict__ sbr) {
    __shared__ float s[256];
    int tid = threadIdx.x;
    float acc = 0.0f;
#pragma unroll
    for (int i = 0; i < 4; i++) acc = __fadd_rn(acc, ill[tid + i * 256]);
    s[tid] = acc;
    __syncthreads();
    for (int st = 128; st > 0; st >>= 1) {
        if (tid < st) s[tid] = __fadd_rn(s[tid], s[tid + st]);
        __syncthreads();
    }
    float area = s[0];
    float scaling = __fdiv_rn(pc[0], area);
    float amb = __fdiv_rn(__fdiv_rn(pc[0], sbr[0]), 1024.0f);
#pragma unroll
    for (int i = 0; i < 4; i++) {
        int n = tid + i * 256;
        g_scaled[n] = fmaxf(__fadd_rn(__fmul_rn(ill[n], scaling), amb), 0.0f);
    }
}

// Pass A: T_stop = max over ALL elements of (first-accept index + 1).
// Knuth-region elements use fake lam = 10000 (JAX lam_rejection).
__global__ void __launch_bounds__(256)
tstop_kernel(const int* __restrict__ labels) {
    __shared__ float s_scaled[N_TBINS];
    __shared__ uint2 s_rs0[TR];
    __shared__ uint2 s_rs1[TR];
    int tid = threadIdx.x;
    int b = blockIdx.x;
    for (int i = tid; i < N_TBINS; i += 256) s_scaled[i] = g_scaled[i];
    if (tid < TR) { s_rs0[tid] = g_rs0[tid]; s_rs1[tid] = g_rs1[tid]; }
    __syncthreads();

    int lab = labels[b];
    int tmax = 0;
#pragma unroll
    for (int i = 0; i < 4; i++) {
        int n = tid + i * 256;
        int src = (n - lab + N_TBINS) & (N_TBINS - 1);
        float lam0 = s_scaled[src];
        float lam = (lam0 < 10.0f) ? 10000.0f : lam0;
        uint32_t j = (uint32_t)b * N_TBINS + (uint32_t)n;
        float log_lam = logf(lam);
        float bb = __fadd_rn(0.931f, __fmul_rn(2.53f, sqrtf(lam)));
        float aa = __fadd_rn(-0.059f, __fmul_rn(0.02483f, bb));
        float inv_alpha = __fadd_rn(1.1239f, __fdiv_rn(1.1328f, __fsub_rn(bb, 3.4f)));
        float v_r = __fsub_rn(0.9277f, __fdiv_rn(3.6224f, __fsub_rn(bb, 2.0f)));
#pragma unroll 1
        for (int t = 0; t < TR; t++) {
            float kc;
            if (rej_step(s_rs0[t], s_rs1[t], j, lam, log_lam, aa, bb, inv_alpha, v_r, kc)) {
                if (t + 1 > tmax) tmax = t + 1;
                break;
            }
        }
    }
    __shared__ int red[256];
    red[tid] = tmax;
    __syncthreads();
    for (int st = 128; st > 0; st >>= 1) {
        if (tid < st) red[tid] = max(red[tid], red[tid + st]);
        __syncthreads();
    }
    if (tid == 0) atomicMax(&g_tstop, red[0]);
}

// Main kernel. Rejection semantics = LAST accept within [0, T_stop),
// implemented as FIRST accept scanning backwards from T_stop-1 (~1.14 steps).
__global__ void __launch_bounds__(256)
poisson_gemm_kernel(const float* __restrict__ W,
                    const int* __restrict__ labels,
                    float* __restrict__ out) {
    __shared__ float s_scaled[N_TBINS];
    __shared__ float s_w[3 * N_TBINS];
    __shared__ uint2 s_ksub[TK];
    __shared__ uint2 s_rs0[TR];
    __shared__ uint2 s_rs1[TR];
    __shared__ int s_tstop;

    int tid = threadIdx.x;
    int b = blockIdx.x;

    for (int i = tid; i < N_TBINS; i += 256) s_scaled[i] = g_scaled[i];
    for (int i = tid; i < 3 * N_TBINS; i += 256) s_w[i] = W[i];
    if (tid < TK) s_ksub[tid] = g_ksub[tid];
    if (tid < TR) { s_rs0[tid] = g_rs0[tid]; s_rs1[tid] = g_rs1[tid]; }
    if (tid == 0) s_tstop = g_tstop;
    __syncthreads();

    int lab = labels[b];
    int tstop = s_tstop;
    float a0 = 0.f, a1 = 0.f, a2 = 0.f;

#pragma unroll
    for (int i = 0; i < 4; i++) {
        int n = tid + i * 256;
        int src = (n - lab + N_TBINS) & (N_TBINS - 1);
        float lam = s_scaled[src];
        uint32_t j = (uint32_t)b * N_TBINS + (uint32_t)n;
        float kval;

        if (lam < 10.0f) {
            // Knuth (bit-validated R5)
            float neg = -lam;
            float lp = 0.0f;
            int k = 0;
#pragma unroll 1
            for (int t = 0; t < TK; t++) {
                if (!(lp > neg)) break;
                k++;
                lp = __fadd_rn(lp, logf(u01(s_ksub[t], j)));
            }
            kval = (float)(k - 1);
        } else {
            // Hormann rejection, last-accept == reverse-scan first accept
            float log_lam = logf(lam);
            float bb = __fadd_rn(0.931f, __fmul_rn(2.53f, sqrtf(lam)));
            float aa = __fadd_rn(-0.059f, __fmul_rn(0.02483f, bb));
            float inv_alpha = __fadd_rn(1.1239f, __fdiv_rn(1.1328f, __fsub_rn(bb, 3.4f)));
            float v_r = __fsub_rn(0.9277f, __fdiv_rn(3.6224f, __fsub_rn(bb, 2.0f)));
            kval = -1.0f;
#pragma unroll 1
            for (int t = tstop - 1; t >= 0; t--) {
                float kc;
                if (rej_step(s_rs0[t], s_rs1[t], j, lam, log_lam, aa, bb,
                             inv_alpha, v_r, kc)) {
                    kval = kc;
                    break;
                }
            }
        }

        a0 = fmaf(kval, s_w[n], a0);
        a1 = fmaf(kval, s_w[N_TBINS + n], a1);
        a2 = fmaf(kval, s_w[2 * N_TBINS + n], a2);
    }

#pragma unroll
    for (int off = 16; off > 0; off >>= 1) {
        a0 += __shfl_xor_sync(0xFFFFFFFFu, a0, off);
        a1 += __shfl_xor_sync(0xFFFFFFFFu, a1, off);
        a2 += __shfl_xor_sync(0xFFFFFFFFu, a2, off);
    }
    __shared__ float wsum[3][8];
    int wid = tid >> 5, lane = tid & 31;
    if (lane == 0) { wsum[0][wid] = a0; wsum[1][wid] = a1; wsum[2][wid] = a2; }
    __syncthreads();
    if (tid < 3) {
        float t = 0.f;
#pragma unroll
        for (int w = 0; w < 8; w++) t += wsum[tid][w];
        out[b * 3 + tid] = t;
    }
}

extern "C" void kernel_launch(void* const* d_in, const int* in_sizes, int n_in,
                              void* d_out, int out_size) {
    const float* ill    = (const float*)d_in[0];
    const float* W      = (const float*)d_in[1];
    const int*   labels = (const int*)d_in[2];
    const float* pc     = (const float*)d_in[3];
    const float* sbr    = (const float*)d_in[4];
    int B = in_sizes[2];

    chains_kernel<<<1, 32>>>();
    setup_kernel<<<1, 256>>>(ill, pc, sbr);
    tstop_kernel<<<B, 256>>>(labels);
    poisson_gemm_kernel<<<B, 256>>>(W, labels, (float*)d_out);
}

// round 8
// speedup vs baseline: 1.2077x; 1.2077x over previous
#include <cuda_runtime.h>
#include <stdint.h>

#define N_TBINS 1024
#define TK 96
#define TR 48

__device__ float g_scaled[N_TBINS];
__device__ uint2 g_ksub[TK];
__device__ uint2 g_rs0[TR];
__device__ uint2 g_rs1[TR];
__device__ int   g_tstop;
__device__ float g_lamfake;   // opaque 10000.0f so device logf/sqrtf run at runtime

__device__ __forceinline__ uint32_t rotl32(uint32_t x, int r) {
    return __funnelshift_l(x, x, r);
}

__device__ __forceinline__ uint2 threefry2x32(uint2 key, uint32_t x0, uint32_t x1) {
    uint32_t ks0 = key.x, ks1 = key.y;
    uint32_t ks2 = ks0 ^ ks1 ^ 0x1BD11BDAu;
    x0 += ks0; x1 += ks1;
#define TF_R(r) { x0 += x1; x1 = rotl32(x1, r); x1 ^= x0; }
    TF_R(13) TF_R(15) TF_R(26) TF_R(6)
    x0 += ks1; x1 += ks2 + 1u;
    TF_R(17) TF_R(29) TF_R(16) TF_R(24)
    x0 += ks2; x1 += ks0 + 2u;
    TF_R(13) TF_R(15) TF_R(26) TF_R(6)
    x0 += ks0; x1 += ks1 + 3u;
    TF_R(17) TF_R(29) TF_R(16) TF_R(24)
    x0 += ks1; x1 += ks2 + 4u;
    TF_R(13) TF_R(15) TF_R(26) TF_R(6)
    x0 += ks2; x1 += ks0 + 5u;
#undef TF_R
    return make_uint2(x0, x1);
}

__device__ __forceinline__ float u01(uint2 key, uint32_t j) {
    uint2 r = threefry2x32(key, 0u, j);
    uint32_t bits = r.x ^ r.y;
    return __uint_as_float((bits >> 9) | 0x3f800000u) - 1.0f;
}

// XLA Lanczos lgamma (g=7), x >= 1 here.
__device__ __forceinline__ float lgamma_xla(float x) {
    float z = __fsub_rn(x, 1.0f);
    float sum = 0.99999999999980993f;
    const float lanc[8] = {
        676.520368121885098567009190444019f,
        -1259.13921672240287047156078755283f,
        771.3234287776530788486528258894f,
        -176.61502916214059906584551354f,
        12.507343278686904814458936853f,
        -0.13857109526572011689554707f,
        9.984369578019570859563e-6f,
        1.50563273514931155834e-7f};
#pragma unroll
    for (int i = 0; i < 8; i++) {
        float denom = __fadd_rn(__fadd_rn(z, (float)i), 1.0f);
        sum = __fadd_rn(sum, __fdiv_rn(lanc[i], denom));
    }
    float t = __fadd_rn(7.5f, z);
    float log_t = __fadd_rn(2.0149030205422647f, log1pf(__fdiv_rn(z, 7.5f)));
    float v = __fmul_rn(__fsub_rn(__fadd_rn(z, 0.5f), __fdiv_rn(t, log_t)), log_t);
    return __fadd_rn(__fadd_rn(0.9189385332046727f, v), logf(sum));
}

// One Hormann rejection iteration.
__device__ __forceinline__ bool rej_step(uint2 s0, uint2 s1, uint32_t j,
                                         float lam, float log_lam, float aa,
                                         float bb, float inv_alpha, float v_r,
                                         float& kc_out) {
    float u = __fsub_rn(u01(s0, j), 0.5f);
    float v = u01(s1, j);
    float us = __fsub_rn(0.5f, fabsf(u));
    float kc = floorf(__fadd_rn(
        __fadd_rn(__fmul_rn(__fadd_rn(__fdiv_rn(__fadd_rn(aa, aa), us), bb), u), lam),
        0.43f));
    kc_out = kc;
    bool accept1 = (us >= 0.07f) && (v <= v_r);
    if (accept1) return true;
    bool reject = (kc < 0.0f) || ((us < 0.013f) && (v > us));
    if (reject) return false;
    float s = logf(__fdiv_rn(__fmul_rn(v, inv_alpha),
                             __fadd_rn(__fdiv_rn(aa, __fmul_rn(us, us)), bb)));
    float tt = __fsub_rn(__fadd_rn(-lam, __fmul_rn(kc, log_lam)),
                         lgamma_xla(__fadd_rn(kc, 1.0f)));
    return s <= tt;
}

// Compute Hormann params exactly as the per-lane code does.
__device__ __forceinline__ void rej_params(float lam, float& log_lam, float& aa,
                                           float& bb, float& inv_alpha, float& v_r) {
    log_lam = logf(lam);
    bb = __fadd_rn(0.931f, __fmul_rn(2.53f, sqrtf(lam)));
    aa = __fadd_rn(-0.059f, __fmul_rn(0.02483f, bb));
    inv_alpha = __fadd_rn(1.1239f, __fdiv_rn(1.1328f, __fsub_rn(bb, 3.4f)));
    v_r = __fsub_rn(0.9277f, __fdiv_rn(3.6224f, __fsub_rn(bb, 2.0f)));
}

__global__ void __launch_bounds__(32, 1)
chains_kernel() {
    if (threadIdx.x != 0) return;
    g_tstop = 0;
    g_lamfake = 10000.0f;
    uint2 key0 = make_uint2(0u, 42u);
    uint2 r = key0;
#pragma unroll 1
    for (int t = 0; t < TK; t++) {
        g_ksub[t] = threefry2x32(r, 0u, 1u);
        r = threefry2x32(r, 0u, 0u);
    }
    uint2 c = key0;
#pragma unroll 1
    for (int t = 0; t < TR; t++) {
        g_rs0[t] = threefry2x32(c, 0u, 1u);
        g_rs1[t] = threefry2x32(c, 0u, 2u);
        c = threefry2x32(c, 0u, 0u);
    }
}

__global__ void __launch_bounds__(256, 1)
setup_kernel(const float* __restrict__ ill,
             const float* __restrict__ pc,
             const float* __restrict__ sbr) {
    __shared__ float s[256];
    int tid = threadIdx.x;
    float acc = 0.0f;
#pragma unroll
    for (int i = 0; i < 4; i++) acc = __fadd_rn(acc, ill[tid + i * 256]);
    s[tid] = acc;
    __syncthreads();
    for (int st = 128; st > 0; st >>= 1) {
        if (tid < st) s[tid] = __fadd_rn(s[tid], s[tid + st]);
        __syncthreads();
    }
    float area = s[0];
    float scaling = __fdiv_rn(pc[0], area);
    float amb = __fdiv_rn(__fdiv_rn(pc[0], sbr[0]), 1024.0f);
#pragma unroll
    for (int i = 0; i < 4; i++) {
        int n = tid + i * 256;
        g_scaled[n] = fmaxf(__fadd_rn(__fmul_rn(ill[n], scaling), amb), 0.0f);
    }
}

// Pass A: T_stop = max over ALL lanes of (first-accept index + 1).
// Fake-lambda lanes (97%) use block-shared precomputed params.
// Flattened 4-chain loop to cut warp divergence.
__global__ void __launch_bounds__(256)
tstop_kernel(const int* __restrict__ labels) {
    __shared__ float s_scaled[N_TBINS];
    __shared__ uint2 s_rs0[TR];
    __shared__ uint2 s_rs1[TR];
    __shared__ float s_fake[6];  // lam, log_lam, aa, bb, inv_alpha, v_r
    int tid = threadIdx.x;
    int b = blockIdx.x;
    for (int i = tid; i < N_TBINS; i += 256) s_scaled[i] = g_scaled[i];
    if (tid < TR) { s_rs0[tid] = g_rs0[tid]; s_rs1[tid] = g_rs1[tid]; }
    if (tid == 0) {
        float lamf = g_lamfake;  // opaque -> runtime device logf/sqrtf
        float ll, aa, bb, ia, vr;
        rej_params(lamf, ll, aa, bb, ia, vr);
        s_fake[0] = lamf; s_fake[1] = ll; s_fake[2] = aa;
        s_fake[3] = bb;   s_fake[4] = ia; s_fake[5] = vr;
    }
    __syncthreads();

    int lab = labels[b];
    float lamv[4]; uint32_t jv[4];
#pragma unroll
    for (int i = 0; i < 4; i++) {
        int n = tid + i * 256;
        int src = (n - lab + N_TBINS) & (N_TBINS - 1);
        lamv[i] = s_scaled[src];
        jv[i] = (uint32_t)b * N_TBINS + (uint32_t)n;
    }

    int tmax = 0;
    int i = 0, t = 0;
    float lam, log_lam, aa, bb, inv_alpha, v_r;
    uint32_t j = jv[0];
    {
        float l0 = lamv[0];
        if (l0 < 10.0f) {
            lam = s_fake[0]; log_lam = s_fake[1]; aa = s_fake[2];
            bb = s_fake[3]; inv_alpha = s_fake[4]; v_r = s_fake[5];
        } else {
            lam = l0; rej_params(lam, log_lam, aa, bb, inv_alpha, v_r);
        }
    }
#pragma unroll 1
    while (i < 4) {
        float kc;
        bool acc = rej_step(s_rs0[t], s_rs1[t], j, lam, log_lam, aa, bb,
                            inv_alpha, v_r, kc);
        t++;
        if (acc || t >= TR) {
            if (acc && t > tmax) tmax = t;
            i++;
            if (i < 4) {
                j = jv[i]; t = 0;
                float l0 = lamv[i];
                if (l0 < 10.0f) {
                    lam = s_fake[0]; log_lam = s_fake[1]; aa = s_fake[2];
                    bb = s_fake[3]; inv_alpha = s_fake[4]; v_r = s_fake[5];
                } else {
                    lam = l0; rej_params(lam, log_lam, aa, bb, inv_alpha, v_r);
                }
            }
        }
    }

    // warp max + one atomic per warp
#pragma unroll
    for (int off = 16; off > 0; off >>= 1)
        tmax = max(tmax, __shfl_xor_sync(0xFFFFFFFFu, tmax, off));
    if ((tid & 31) == 0) atomicMax(&g_tstop, tmax);
}

// Main: flattened Knuth (4 chains/thread, one threefry per loop iter),
// rejection lanes = reverse-scan last-accept; fused 3-tap GEMM.
__global__ void __launch_bounds__(256)
poisson_gemm_kernel(const float* __restrict__ W,
                    const int* __restrict__ labels,
                    float* __restrict__ out) {
    __shared__ float s_scaled[N_TBINS];
    __shared__ float s_w[3 * N_TBINS];
    __shared__ uint2 s_ksub[TK];
    __shared__ uint2 s_rs0[TR];
    __shared__ uint2 s_rs1[TR];
    __shared__ int s_tstop;

    int tid = threadIdx.x;
    int b = blockIdx.x;

    for (int i = tid; i < N_TBINS; i += 256) s_scaled[i] = g_scaled[i];
    for (int i = tid; i < 3 * N_TBINS; i += 256) s_w[i] = W[i];
    if (tid < TK) s_ksub[tid] = g_ksub[tid];
    if (tid < TR) { s_rs0[tid] = g_rs0[tid]; s_rs1[tid] = g_rs1[tid]; }
    if (tid == 0) s_tstop = g_tstop;
    __syncthreads();

    int lab = labels[b];
    float lamv[4]; uint32_t jv[4]; float kv[4];
#pragma unroll
    for (int i = 0; i < 4; i++) {
        int n = tid + i * 256;
        int src = (n - lab + N_TBINS) & (N_TBINS - 1);
        lamv[i] = s_scaled[src];
        jv[i] = (uint32_t)b * N_TBINS + (uint32_t)n;
        kv[i] = 0.0f;
    }
    int tstop = s_tstop;

    // ---- flattened Knuth over lanes with lam < 10 ----
    int i = 0;
    while (i < 4 && !(lamv[i] < 10.0f)) i++;
    float neg = 0.f, lp = 0.f; int k = 0;
    uint32_t j = 0;
    if (i < 4) { neg = -lamv[i]; lp = 0.f; k = 0; j = jv[i]; }
#pragma unroll 1
    while (i < 4) {
        if (lp > neg && k < TK) {
            lp = __fadd_rn(lp, logf(u01(s_ksub[k], j)));
            k++;
        } else {
            kv[i] = (float)(k - 1);
            i++;
            while (i < 4 && !(lamv[i] < 10.0f)) i++;
            if (i < 4) { neg = -lamv[i]; lp = 0.f; k = 0; j = jv[i]; }
        }
    }

    // ---- rejection lanes: last accept within [0,tstop) via reverse scan ----
#pragma unroll
    for (int i2 = 0; i2 < 4; i2++) {
        if (!(lamv[i2] < 10.0f)) {
            float lam = lamv[i2];
            float log_lam, aa, bb, inv_alpha, v_r;
            rej_params(lam, log_lam, aa, bb, inv_alpha, v_r);
            float kval = -1.0f;
#pragma unroll 1
            for (int t = tstop - 1; t >= 0; t--) {
                float kc;
                if (rej_step(s_rs0[t], s_rs1[t], jv[i2], lam, log_lam, aa, bb,
                             inv_alpha, v_r, kc)) {
                    kval = kc;
                    break;
                }
            }
            kv[i2] = kval;
        }
    }

    // ---- fused 3-output GEMM ----
    float a0 = 0.f, a1 = 0.f, a2 = 0.f;
#pragma unroll
    for (int i2 = 0; i2 < 4; i2++) {
        int n = tid + i2 * 256;
        a0 = fmaf(kv[i2], s_w[n], a0);
        a1 = fmaf(kv[i2], s_w[N_TBINS + n], a1);
        a2 = fmaf(kv[i2], s_w[2 * N_TBINS + n], a2);
    }

#pragma unroll
    for (int off = 16; off > 0; off >>= 1) {
        a0 += __shfl_xor_sync(0xFFFFFFFFu, a0, off);
        a1 += __shfl_xor_sync(0xFFFFFFFFu, a1, off);
        a2 += __shfl_xor_sync(0xFFFFFFFFu, a2, off);
    }
    __shared__ float wsum[3][8];
    int wid = tid >> 5, lane = tid & 31;
    if (lane == 0) { wsum[0][wid] = a0; wsum[1][wid] = a1; wsum[2][wid] = a2; }
    __syncthreads();
    if (tid < 3) {
        float t = 0.f;
#pragma unroll
        for (int w = 0; w < 8; w++) t += wsum[tid][w];
        out[b * 3 + tid] = t;
    }
}

extern "C" void kernel_launch(void* const* d_in, const int* in_sizes, int n_in,
                              void* d_out, int out_size) {
    const float* ill    = (const float*)d_in[0];
    const float* W      = (const float*)d_in[1];
    const int*   labels = (const int*)d_in[2];
    const float* pc     = (const float*)d_in[3];
    const float* sbr    = (const float*)d_in[4];
    int B = in_sizes[2];

    chains_kernel<<<1, 32>>>();
    setup_kernel<<<1, 256>>>(ill, pc, sbr);
    tstop_kernel<<<B, 256>>>(labels);
    poisson_gemm_kernel<<<B, 256>>>(W, labels, (float*)d_out);
}

// round 9
// speedup vs baseline: 1.2531x; 1.0375x over previous
#include <cuda_runtime.h>
#include <stdint.h>

#define N_TBINS 1024
#define TK 96
#define TR 48

__device__ float g_scaled[N_TBINS];
__device__ uint2 g_ksub[TK];
__device__ uint2 g_rs0[TR];
__device__ uint2 g_rs1[TR];
__device__ int   g_tstop;
__device__ float g_lamfake;   // opaque 10000.0f -> runtime device logf/sqrtf

__device__ __forceinline__ uint32_t rotl32(uint32_t x, int r) {
    return __funnelshift_l(x, x, r);
}

__device__ __forceinline__ uint2 threefry2x32(uint2 key, uint32_t x0, uint32_t x1) {
    uint32_t ks0 = key.x, ks1 = key.y;
    uint32_t ks2 = ks0 ^ ks1 ^ 0x1BD11BDAu;
    x0 += ks0; x1 += ks1;
#define TF_R(r) { x0 += x1; x1 = rotl32(x1, r); x1 ^= x0; }
    TF_R(13) TF_R(15) TF_R(26) TF_R(6)
    x0 += ks1; x1 += ks2 + 1u;
    TF_R(17) TF_R(29) TF_R(16) TF_R(24)
    x0 += ks2; x1 += ks0 + 2u;
    TF_R(13) TF_R(15) TF_R(26) TF_R(6)
    x0 += ks0; x1 += ks1 + 3u;
    TF_R(17) TF_R(29) TF_R(16) TF_R(24)
    x0 += ks1; x1 += ks2 + 4u;
    TF_R(13) TF_R(15) TF_R(26) TF_R(6)
    x0 += ks2; x1 += ks0 + 5u;
#undef TF_R
    return make_uint2(x0, x1);
}

__device__ __forceinline__ float u01(uint2 key, uint32_t j) {
    uint2 r = threefry2x32(key, 0u, j);
    uint32_t bits = r.x ^ r.y;
    return __uint_as_float((bits >> 9) | 0x3f800000u) - 1.0f;
}

// XLA Lanczos lgamma (g=7), x >= 1 here.
__device__ __forceinline__ float lgamma_xla(float x) {
    float z = __fsub_rn(x, 1.0f);
    float sum = 0.99999999999980993f;
    const float lanc[8] = {
        676.520368121885098567009190444019f,
        -1259.13921672240287047156078755283f,
        771.3234287776530788486528258894f,
        -176.61502916214059906584551354f,
        12.507343278686904814458936853f,
        -0.13857109526572011689554707f,
        9.984369578019570859563e-6f,
        1.50563273514931155834e-7f};
#pragma unroll
    for (int i = 0; i < 8; i++) {
        float denom = __fadd_rn(__fadd_rn(z, (float)i), 1.0f);
        sum = __fadd_rn(sum, __fdiv_rn(lanc[i], denom));
    }
    float t = __fadd_rn(7.5f, z);
    float log_t = __fadd_rn(2.0149030205422647f, log1pf(__fdiv_rn(z, 7.5f)));
    float v = __fmul_rn(__fsub_rn(__fadd_rn(z, 0.5f), __fdiv_rn(t, log_t)), log_t);
    return __fadd_rn(__fadd_rn(0.9189385332046727f, v), logf(sum));
}

__device__ __forceinline__ bool rej_step(uint2 s0, uint2 s1, uint32_t j,
                                         float lam, float log_lam, float aa,
                                         float bb, float inv_alpha, float v_r,
                                         float& kc_out) {
    float u = __fsub_rn(u01(s0, j), 0.5f);
    float v = u01(s1, j);
    float us = __fsub_rn(0.5f, fabsf(u));
    float kc = floorf(__fadd_rn(
        __fadd_rn(__fmul_rn(__fadd_rn(__fdiv_rn(__fadd_rn(aa, aa), us), bb), u), lam),
        0.43f));
    kc_out = kc;
    bool accept1 = (us >= 0.07f) && (v <= v_r);
    if (accept1) return true;
    bool reject = (kc < 0.0f) || ((us < 0.013f) && (v > us));
    if (reject) return false;
    float s = logf(__fdiv_rn(__fmul_rn(v, inv_alpha),
                             __fadd_rn(__fdiv_rn(aa, __fmul_rn(us, us)), bb)));
    float tt = __fsub_rn(__fadd_rn(-lam, __fmul_rn(kc, log_lam)),
                         lgamma_xla(__fadd_rn(kc, 1.0f)));
    return s <= tt;
}

__device__ __forceinline__ void rej_params(float lam, float& log_lam, float& aa,
                                           float& bb, float& inv_alpha, float& v_r) {
    log_lam = logf(lam);
    bb = __fadd_rn(0.931f, __fmul_rn(2.53f, sqrtf(lam)));
    aa = __fadd_rn(-0.059f, __fmul_rn(0.02483f, bb));
    inv_alpha = __fadd_rn(1.1239f, __fdiv_rn(1.1328f, __fsub_rn(bb, 3.4f)));
    v_r = __fsub_rn(0.9277f, __fdiv_rn(3.6224f, __fsub_rn(bb, 2.0f)));
}

__global__ void __launch_bounds__(32, 1)
chains_kernel() {
    if (threadIdx.x != 0) return;
    g_tstop = 0;
    g_lamfake = 10000.0f;
    uint2 key0 = make_uint2(0u, 42u);
    uint2 r = key0;
#pragma unroll 1
    for (int t = 0; t < TK; t++) {
        g_ksub[t] = threefry2x32(r, 0u, 1u);
        r = threefry2x32(r, 0u, 0u);
    }
    uint2 c = key0;
#pragma unroll 1
    for (int t = 0; t < TR; t++) {
        g_rs0[t] = threefry2x32(c, 0u, 1u);
        g_rs1[t] = threefry2x32(c, 0u, 2u);
        c = threefry2x32(c, 0u, 0u);
    }
}

__global__ void __launch_bounds__(256, 1)
setup_kernel(const float* __restrict__ ill,
             const float* __restrict__ pc,
             const float* __restrict__ sbr) {
    __shared__ float s[256];
    int tid = threadIdx.x;
    float acc = 0.0f;
#pragma unroll
    for (int i = 0; i < 4; i++) acc = __fadd_rn(acc, ill[tid + i * 256]);
    s[tid] = acc;
    __syncthreads();
    for (int st = 128; st > 0; st >>= 1) {
        if (tid < st) s[tid] = __fadd_rn(s[tid], s[tid + st]);
        __syncthreads();
    }
    float area = s[0];
    float scaling = __fdiv_rn(pc[0], area);
    float amb = __fdiv_rn(__fdiv_rn(pc[0], sbr[0]), 1024.0f);
#pragma unroll
    for (int i = 0; i < 4; i++) {
        int n = tid + i * 256;
        g_scaled[n] = fmaxf(__fadd_rn(__fmul_rn(ill[n], scaling), amb), 0.0f);
    }
}

// Pass A: T_stop via warp work-stealing over each warp's 128 bins.
__global__ void __launch_bounds__(256)
tstop_kernel(const int* __restrict__ labels) {
    __shared__ float s_scaled[N_TBINS];
    __shared__ uint2 s_rs0[TR];
    __shared__ uint2 s_rs1[TR];
    __shared__ float s_fake[6];
    __shared__ int s_cur[8];
    int tid = threadIdx.x;
    int b = blockIdx.x;
    int wid = tid >> 5, lane = tid & 31;
    for (int i = tid; i < N_TBINS; i += 256) s_scaled[i] = g_scaled[i];
    if (tid < TR) { s_rs0[tid] = g_rs0[tid]; s_rs1[tid] = g_rs1[tid]; }
    if (tid < 8) s_cur[tid] = 32;
    if (tid == 0) {
        float lamf = g_lamfake;
        float ll, aa, bb, ia, vr;
        rej_params(lamf, ll, aa, bb, ia, vr);
        s_fake[0] = lamf; s_fake[1] = ll; s_fake[2] = aa;
        s_fake[3] = bb;   s_fake[4] = ia; s_fake[5] = vr;
    }
    __syncthreads();

    int lab = labels[b];
    uint32_t jbase = (uint32_t)b * N_TBINS;
    int tmax = 0;

    // per-lane state
    float lam, log_lam, aa, bb, inv_alpha, v_r;
    uint32_t j = 0;
    int t = 0;
    bool active = false;

    int rel = lane;
    // start first bin
    {
        int n = wid * 128 + rel;
        int src = (n - lab + N_TBINS) & (N_TBINS - 1);
        float l0 = s_scaled[src];
        if (l0 < 10.0f) {
            lam = s_fake[0]; log_lam = s_fake[1]; aa = s_fake[2];
            bb = s_fake[3]; inv_alpha = s_fake[4]; v_r = s_fake[5];
        } else {
            lam = l0; rej_params(lam, log_lam, aa, bb, inv_alpha, v_r);
        }
        j = jbase + (uint32_t)n; t = 0; active = true;
    }

#pragma unroll 1
    while (__ballot_sync(0xFFFFFFFFu, active)) {
        if (active) {
            float kc;
            bool acc = rej_step(s_rs0[t], s_rs1[t], j, lam, log_lam, aa, bb,
                                inv_alpha, v_r, kc);
            t++;
            if (acc || t >= TR) {
                if (acc && t > tmax) tmax = t;
                int r = atomicAdd(&s_cur[wid], 1);
                if (r >= 128) {
                    active = false;
                } else {
                    int n = wid * 128 + r;
                    int src = (n - lab + N_TBINS) & (N_TBINS - 1);
                    float l0 = s_scaled[src];
                    if (l0 < 10.0f) {
                        lam = s_fake[0]; log_lam = s_fake[1]; aa = s_fake[2];
                        bb = s_fake[3]; inv_alpha = s_fake[4]; v_r = s_fake[5];
                    } else {
                        lam = l0; rej_params(lam, log_lam, aa, bb, inv_alpha, v_r);
                    }
                    j = jbase + (uint32_t)n; t = 0;
                }
            }
        }
    }

#pragma unroll
    for (int off = 16; off > 0; off >>= 1)
        tmax = max(tmax, __shfl_xor_sync(0xFFFFFFFFu, tmax, off));
    if (lane == 0) atomicMax(&g_tstop, tmax);
}

// Main: warp work-stealing Knuth + rejection phase + fused GEMM.
__global__ void __launch_bounds__(256)
poisson_gemm_kernel(const float* __restrict__ W,
                    const int* __restrict__ labels,
                    float* __restrict__ out) {
    __shared__ float s_scaled[N_TBINS];
    __shared__ float s_w[3 * N_TBINS];
    __shared__ float s_k[N_TBINS];
    __shared__ uint2 s_ksub[TK];
    __shared__ uint2 s_rs0[TR];
    __shared__ uint2 s_rs1[TR];
    __shared__ int s_cur[8];
    __shared__ int s_tstop;

    int tid = threadIdx.x;
    int b = blockIdx.x;
    int wid = tid >> 5, lane = tid & 31;

    for (int i = tid; i < N_TBINS; i += 256) s_scaled[i] = g_scaled[i];
    for (int i = tid; i < 3 * N_TBINS; i += 256) s_w[i] = W[i];
    if (tid < TK) s_ksub[tid] = g_ksub[tid];
    if (tid < TR) { s_rs0[tid] = g_rs0[tid]; s_rs1[tid] = g_rs1[tid]; }
    if (tid < 8) s_cur[tid] = 32;
    if (tid == 0) s_tstop = g_tstop;
    __syncthreads();

    int lab = labels[b];
    uint32_t jbase = (uint32_t)b * N_TBINS;

    // ---- phase 1: dynamic Knuth over this warp's 128 bins ----
    float lp = 0.f, neg = 0.f;
    int k = 0, rel = -1;
    uint32_t j = 0;
    bool active = false;

    // start: claim bins until a knuth bin or exhausted
    {
        int r = lane;
        while (true) {
            if (r >= 128) { active = false; break; }
            int n = wid * 128 + r;
            int src = (n - lab + N_TBINS) & (N_TBINS - 1);
            float l0 = s_scaled[src];
            if (l0 < 10.0f) {
                neg = -l0; lp = 0.f; k = 0; j = jbase + (uint32_t)n;
                rel = r; active = true; break;
            }
            r = atomicAdd(&s_cur[wid], 1);
        }
    }

#pragma unroll 1
    while (__ballot_sync(0xFFFFFFFFu, active)) {
        if (active) {
            if (lp > neg && k < TK) {
                lp = __fadd_rn(lp, logf(u01(s_ksub[k], j)));
                k++;
            } else {
                s_k[wid * 128 + rel] = (float)(k - 1);
                int r = atomicAdd(&s_cur[wid], 1);
                while (true) {
                    if (r >= 128) { active = false; break; }
                    int n = wid * 128 + r;
                    int src = (n - lab + N_TBINS) & (N_TBINS - 1);
                    float l0 = s_scaled[src];
                    if (l0 < 10.0f) {
                        neg = -l0; lp = 0.f; k = 0; j = jbase + (uint32_t)n;
                        rel = r; break;
                    }
                    r = atomicAdd(&s_cur[wid], 1);
                }
            }
        }
    }

    // ---- phase 2: rejection bins (strided), last-accept via reverse scan ----
    int tstop = s_tstop;
#pragma unroll
    for (int i = 0; i < 4; i++) {
        int n = tid + i * 256;
        int src = (n - lab + N_TBINS) & (N_TBINS - 1);
        float lam = s_scaled[src];
        if (!(lam < 10.0f)) {
            float log_lam, aa, bb, inv_alpha, v_r;
            rej_params(lam, log_lam, aa, bb, inv_alpha, v_r);
            float kval = -1.0f;
            uint32_t jj = jbase + (uint32_t)n;
#pragma unroll 1
            for (int t = tstop - 1; t >= 0; t--) {
                float kc;
                if (rej_step(s_rs0[t], s_rs1[t], jj, lam, log_lam, aa, bb,
                             inv_alpha, v_r, kc)) {
                    kval = kc;
                    break;
                }
            }
            s_k[n] = kval;
        }
    }
    __syncthreads();

    // ---- phase 3: fused 3-output GEMM ----
    float a0 = 0.f, a1 = 0.f, a2 = 0.f;
#pragma unroll
    for (int i = 0; i < 4; i++) {
        int n = tid + i * 256;
        float kv = s_k[n];
        a0 = fmaf(kv, s_w[n], a0);
        a1 = fmaf(kv, s_w[N_TBINS + n], a1);
        a2 = fmaf(kv, s_w[2 * N_TBINS + n], a2);
    }

#pragma unroll
    for (int off = 16; off > 0; off >>= 1) {
        a0 += __shfl_xor_sync(0xFFFFFFFFu, a0, off);
        a1 += __shfl_xor_sync(0xFFFFFFFFu, a1, off);
        a2 += __shfl_xor_sync(0xFFFFFFFFu, a2, off);
    }
    __shared__ float wsum[3][8];
    if (lane == 0) { wsum[0][wid] = a0; wsum[1][wid] = a1; wsum[2][wid] = a2; }
    __syncthreads();
    if (tid < 3) {
        float t = 0.f;
#pragma unroll
        for (int w = 0; w < 8; w++) t += wsum[tid][w];
        out[b * 3 + tid] = t;
    }
}

extern "C" void kernel_launch(void* const* d_in, const int* in_sizes, int n_in,
                              void* d_out, int out_size) {
    const float* ill    = (const float*)d_in[0];
    const float* W      = (const float*)d_in[1];
    const int*   labels = (const int*)d_in[2];
    const float* pc     = (const float*)d_in[3];
    const float* sbr    = (const float*)d_in[4];
    int B = in_sizes[2];

    chains_kernel<<<1, 32>>>();
    setup_kernel<<<1, 256>>>(ill, pc, sbr);
    tstop_kernel<<<B, 256>>>(labels);
    poisson_gemm_kernel<<<B, 256>>>(W, labels, (float*)d_out);
}

// round 11
// speedup vs baseline: 1.4115x; 1.1264x over previous
#include <cuda_runtime.h>
#include <stdint.h>

#define N_TBINS 1024
#define TK 96
#define TR 48
#define TT_LO 9000
#define TT_N  2001
#define MAXB  32768

__device__ float g_scaled[N_TBINS];
__device__ uint2 g_ksub[TK];
__device__ uint2 g_rs0[TR];
__device__ uint2 g_rs1[TR];
__device__ int   g_tstop;
__device__ float g_lamfake = 10000.0f;  // opaque to the compiler
__device__ float g_tt[TT_N];
__device__ float g_partial[MAXB * 3];

__device__ __forceinline__ uint32_t rotl32(uint32_t x, int r) {
    return __funnelshift_l(x, x, r);
}

__device__ __forceinline__ uint2 threefry2x32(uint2 key, uint32_t x0, uint32_t x1) {
    uint32_t ks0 = key.x, ks1 = key.y;
    uint32_t ks2 = ks0 ^ ks1 ^ 0x1BD11BDAu;
    x0 += ks0; x1 += ks1;
#define TF_R(r) { x0 += x1; x1 = rotl32(x1, r); x1 ^= x0; }
    TF_R(13) TF_R(15) TF_R(26) TF_R(6)
    x0 += ks1; x1 += ks2 + 1u;
    TF_R(17) TF_R(29) TF_R(16) TF_R(24)
    x0 += ks2; x1 += ks0 + 2u;
    TF_R(13) TF_R(15) TF_R(26) TF_R(6)
    x0 += ks0; x1 += ks1 + 3u;
    TF_R(17) TF_R(29) TF_R(16) TF_R(24)
    x0 += ks1; x1 += ks2 + 4u;
    TF_R(13) TF_R(15) TF_R(26) TF_R(6)
    x0 += ks2; x1 += ks0 + 5u;
#undef TF_R
    return make_uint2(x0, x1);
}

__device__ __forceinline__ float u01(uint2 key, uint32_t j) {
    uint2 r = threefry2x32(key, 0u, j);
    uint32_t bits = r.x ^ r.y;
    return __uint_as_float((bits >> 9) | 0x3f800000u) - 1.0f;
}

// XLA Lanczos lgamma (g=7), x >= 1 here.
__device__ __forceinline__ float lgamma_xla(float x) {
    float z = __fsub_rn(x, 1.0f);
    float sum = 0.99999999999980993f;
    const float lanc[8] = {
        676.520368121885098567009190444019f,
        -1259.13921672240287047156078755283f,
        771.3234287776530788486528258894f,
        -176.61502916214059906584551354f,
        12.507343278686904814458936853f,
        -0.13857109526572011689554707f,
        9.984369578019570859563e-6f,
        1.50563273514931155834e-7f};
#pragma unroll
    for (int i = 0; i < 8; i++) {
        float denom = __fadd_rn(__fadd_rn(z, (float)i), 1.0f);
        sum = __fadd_rn(sum, __fdiv_rn(lanc[i], denom));
    }
    float t = __fadd_rn(7.5f, z);
    float log_t = __fadd_rn(2.0149030205422647f, log1pf(__fdiv_rn(z, 7.5f)));
    float v = __fmul_rn(__fsub_rn(__fadd_rn(z, 0.5f), __fdiv_rn(t, log_t)), log_t);
    return __fadd_rn(__fadd_rn(0.9189385332046727f, v), logf(sum));
}

// One Hormann rejection iteration; use_table => fake-lambda tt lookup.
__device__ __forceinline__ bool rej_step(uint2 s0, uint2 s1, uint32_t j,
                                         float lam, float log_lam, float aa,
                                         float bb, float inv_alpha, float v_r,
                                         bool use_table, float& kc_out) {
    float u = __fsub_rn(u01(s0, j), 0.5f);
    float v = u01(s1, j);
    float us = __fsub_rn(0.5f, fabsf(u));
    float kc = floorf(__fadd_rn(
        __fadd_rn(__fmul_rn(__fadd_rn(__fdiv_rn(__fadd_rn(aa, aa), us), bb), u), lam),
        0.43f));
    kc_out = kc;
    bool accept1 = (us >= 0.07f) && (v <= v_r);
    if (accept1) return true;
    bool reject = (kc < 0.0f) || ((us < 0.013f) && (v > us));
    if (reject) return false;
    float s = logf(__fdiv_rn(__fmul_rn(v, inv_alpha),
                             __fadd_rn(__fdiv_rn(aa, __fmul_rn(us, us)), bb)));
    float tt;
    if (use_table && kc >= (float)TT_LO && kc <= (float)(TT_LO + TT_N - 1)) {
        tt = __ldg(&g_tt[(int)kc - TT_LO]);
    } else {
        tt = __fsub_rn(__fadd_rn(-lam, __fmul_rn(kc, log_lam)),
                       lgamma_xla(__fadd_rn(kc, 1.0f)));
    }
    return s <= tt;
}

__device__ __forceinline__ void rej_params(float lam, float& log_lam, float& aa,
                                           float& bb, float& inv_alpha, float& v_r) {
    log_lam = logf(lam);
    bb = __fadd_rn(0.931f, __fmul_rn(2.53f, sqrtf(lam)));
    aa = __fadd_rn(-0.059f, __fmul_rn(0.02483f, bb));
    inv_alpha = __fadd_rn(1.1239f, __fdiv_rn(1.1328f, __fsub_rn(bb, 3.4f)));
    v_r = __fsub_rn(0.9277f, __fdiv_rn(3.6224f, __fsub_rn(bb, 2.0f)));
}

// chains + tt table. 256 threads: t0 does sequential chains; all build table.
__global__ void __launch_bounds__(256, 1)
chains_kernel() {
    int tid = threadIdx.x;
    if (tid == 0) {
        g_tstop = 0;
        uint2 key0 = make_uint2(0u, 42u);
        uint2 r = key0;
#pragma unroll 1
        for (int t = 0; t < TK; t++) {
            g_ksub[t] = threefry2x32(r, 0u, 1u);
            r = threefry2x32(r, 0u, 0u);
        }
        uint2 c = key0;
#pragma unroll 1
        for (int t = 0; t < TR; t++) {
            g_rs0[t] = threefry2x32(c, 0u, 1u);
            g_rs1[t] = threefry2x32(c, 0u, 2u);
            c = threefry2x32(c, 0u, 0u);
        }
    }
    float lamf = g_lamfake;
    float log_lam = logf(lamf);
#pragma unroll 1
    for (int m = tid; m < TT_N; m += 256) {
        float kc = (float)(TT_LO + m);
        g_tt[m] = __fsub_rn(__fadd_rn(-lamf, __fmul_rn(kc, log_lam)),
                            lgamma_xla(__fadd_rn(kc, 1.0f)));
    }
}

__global__ void __launch_bounds__(256, 1)
setup_kernel(const float* __restrict__ ill,
             const float* __restrict__ pc,
             const float* __restrict__ sbr) {
    __shared__ float s[256];
    int tid = threadIdx.x;
    float acc = 0.0f;
#pragma unroll
    for (int i = 0; i < 4; i++) acc = __fadd_rn(acc, ill[tid + i * 256]);
    s[tid] = acc;
    __syncthreads();
    for (int st = 128; st > 0; st >>= 1) {
        if (tid < st) s[tid] = __fadd_rn(s[tid], s[tid + st]);
        __syncthreads();
    }
    float area = s[0];
    float scaling = __fdiv_rn(pc[0], area);
    float amb = __fdiv_rn(__fdiv_rn(pc[0], sbr[0]), 1024.0f);
#pragma unroll
    for (int i = 0; i < 4; i++) {
        int n = tid + i * 256;
        g_scaled[n] = fmaxf(__fadd_rn(__fmul_rn(ill[n], scaling), amb), 0.0f);
    }
}

// Kernel A: per row — (0) first-accept scan of all 1024 bins (fake lam for
// knuth bins, real lam for rejection bins) -> atomicMax tstop;
// (1) work-stealing Knuth for lam<10 bins; (2) Knuth-only partial GEMM.
__global__ void __launch_bounds__(256)
main_kernel(const float* __restrict__ W, const int* __restrict__ labels) {
    __shared__ float s_scaled[N_TBINS];
    __shared__ float s_k[N_TBINS];
    __shared__ uint2 s_ksub[TK];
    __shared__ uint2 s_rs0[TR];
    __shared__ uint2 s_rs1[TR];
    __shared__ float s_fake[6];
    __shared__ int s_cur[8];
    __shared__ int s_cur2[8];

    int tid = threadIdx.x;
    int b = blockIdx.x;
    int wid = tid >> 5, lane = tid & 31;

    for (int i = tid; i < N_TBINS; i += 256) s_scaled[i] = g_scaled[i];
    if (tid < TK) s_ksub[tid] = g_ksub[tid];
    if (tid < TR) { s_rs0[tid] = g_rs0[tid]; s_rs1[tid] = g_rs1[tid]; }
    if (tid < 8) { s_cur[tid] = 32; s_cur2[tid] = 32; }
    if (tid == 0) {
        float lamf = g_lamfake;
        float ll, aa, bb, ia, vr;
        rej_params(lamf, ll, aa, bb, ia, vr);
        s_fake[0] = lamf; s_fake[1] = ll; s_fake[2] = aa;
        s_fake[3] = bb;   s_fake[4] = ia; s_fake[5] = vr;
    }
    __syncthreads();

    int lab = labels[b];
    uint32_t jbase = (uint32_t)b * N_TBINS;

    // ---- phase 0: first-accept scan, work-stealing over warp's 128 bins ----
    {
        int tmax = 0;
        float lam, log_lam, aa, bb, inv_alpha, v_r;
        bool use_table = true;
        uint32_t j = 0;
        int t = 0;
        bool active = true;
        {
            int n = wid * 128 + lane;
            int src = (n - lab + N_TBINS) & (N_TBINS - 1);
            float l0 = s_scaled[src];
            if (l0 < 10.0f) {
                lam = s_fake[0]; log_lam = s_fake[1]; aa = s_fake[2];
                bb = s_fake[3]; inv_alpha = s_fake[4]; v_r = s_fake[5];
                use_table = true;
            } else {
                lam = l0; rej_params(lam, log_lam, aa, bb, inv_alpha, v_r);
                use_table = false;
            }
            j = jbase + (uint32_t)n; t = 0;
        }
#pragma unroll 1
        while (__ballot_sync(0xFFFFFFFFu, active)) {
            if (active) {
                float kc;
                bool acc = rej_step(s_rs0[t], s_rs1[t], j, lam, log_lam, aa, bb,
                                    inv_alpha, v_r, use_table, kc);
                t++;
                if (acc || t >= TR) {
                    if (acc && t > tmax) tmax = t;
                    int r = atomicAdd(&s_cur[wid], 1);
                    if (r >= 128) {
                        active = false;
                    } else {
                        int n = wid * 128 + r;
                        int src = (n - lab + N_TBINS) & (N_TBINS - 1);
                        float l0 = s_scaled[src];
                        if (l0 < 10.0f) {
                            lam = s_fake[0]; log_lam = s_fake[1]; aa = s_fake[2];
                            bb = s_fake[3]; inv_alpha = s_fake[4]; v_r = s_fake[5];
                            use_table = true;
                        } else {
                            lam = l0; rej_params(lam, log_lam, aa, bb, inv_alpha, v_r);
                            use_table = false;
                        }
                        j = jbase + (uint32_t)n; t = 0;
                    }
                }
            }
        }
#pragma unroll
        for (int off = 16; off > 0; off >>= 1)
            tmax = max(tmax, __shfl_xor_sync(0xFFFFFFFFu, tmax, off));
        if (lane == 0) atomicMax(&g_tstop, tmax);
    }

    // ---- phase 1: work-stealing Knuth over lam<10 bins ----
    {
        float lp = 0.f, neg = 0.f;
        int k = 0, rel = -1;
        uint32_t j = 0;
        bool active = false;
        {
            int r = lane;
            while (true) {
                if (r >= 128) { active = false; break; }
                int n = wid * 128 + r;
                int src = (n - lab + N_TBINS) & (N_TBINS - 1);
                float l0 = s_scaled[src];
                if (l0 < 10.0f) {
                    neg = -l0; lp = 0.f; k = 0; j = jbase + (uint32_t)n;
                    rel = r; active = true; break;
                }
                s_k[n] = 0.0f;  // rejection bin: zero for partial GEMM
                r = atomicAdd(&s_cur2[wid], 1);
            }
        }
#pragma unroll 1
        while (__ballot_sync(0xFFFFFFFFu, active)) {
            if (active) {
                if (lp > neg && k < TK) {
                    lp = __fadd_rn(lp, logf(u01(s_ksub[k], j)));
                    k++;
                } else {
                    s_k[wid * 128 + rel] = (float)(k - 1);
                    int r = atomicAdd(&s_cur2[wid], 1);
                    while (true) {
                        if (r >= 128) { active = false; break; }
                        int n = wid * 128 + r;
                        int src = (n - lab + N_TBINS) & (N_TBINS - 1);
                        float l0 = s_scaled[src];
                        if (l0 < 10.0f) {
                            neg = -l0; lp = 0.f; k = 0; j = jbase + (uint32_t)n;
                            rel = r; break;
                        }
                        s_k[n] = 0.0f;
                        r = atomicAdd(&s_cur2[wid], 1);
                    }
                }
            }
        }
    }
    __syncthreads();

    // ---- phase 2: Knuth-only partial GEMM ----
    float a0 = 0.f, a1 = 0.f, a2 = 0.f;
#pragma unroll
    for (int i = 0; i < 4; i++) {
        int n = tid + i * 256;
        float kv = s_k[n];
        a0 = fmaf(kv, __ldg(&W[n]), a0);
        a1 = fmaf(kv, __ldg(&W[N_TBINS + n]), a1);
        a2 = fmaf(kv, __ldg(&W[2 * N_TBINS + n]), a2);
    }
#pragma unroll
    for (int off = 16; off > 0; off >>= 1) {
        a0 += __shfl_xor_sync(0xFFFFFFFFu, a0, off);
        a1 += __shfl_xor_sync(0xFFFFFFFFu, a1, off);
        a2 += __shfl_xor_sync(0xFFFFFFFFu, a2, off);
    }
    __shared__ float wsum[3][8];
    if (lane == 0) { wsum[0][wid] = a0; wsum[1][wid] = a1; wsum[2][wid] = a2; }
    __syncthreads();
    if (tid < 3) {
        float t = 0.f;
#pragma unroll
        for (int w = 0; w < 8; w++) t += wsum[tid][w];
        g_partial[b * 3 + tid] = t;
    }
}

// Kernel B: rejection bins only — reverse-scan last-accept + add partials.
__global__ void __launch_bounds__(256)
finish_kernel(const float* __restrict__ W,
              const int* __restrict__ labels,
              float* __restrict__ out) {
    __shared__ float s_scaled[N_TBINS];
    __shared__ uint2 s_rs0[TR];
    __shared__ uint2 s_rs1[TR];
    __shared__ int s_list[N_TBINS];
    __shared__ int s_cnt;
    __shared__ int s_tstop;

    int tid = threadIdx.x;
    int b = blockIdx.x;
    for (int i = tid; i < N_TBINS; i += 256) s_scaled[i] = g_scaled[i];
    if (tid < TR) { s_rs0[tid] = g_rs0[tid]; s_rs1[tid] = g_rs1[tid]; }
    if (tid == 0) { s_cnt = 0; s_tstop = g_tstop; }
    __syncthreads();

    int lab = labels[b];
    uint32_t jbase = (uint32_t)b * N_TBINS;
#pragma unroll
    for (int i = 0; i < 4; i++) {
        int n = tid + i * 256;
        int src = (n - lab + N_TBINS) & (N_TBINS - 1);
        if (!(s_scaled[src] < 10.0f)) {
            int e = atomicAdd(&s_cnt, 1);
            s_list[e] = n;
        }
    }
    __syncthreads();

    int cnt = s_cnt;
    int tstop = s_tstop;
    float a0 = 0.f, a1 = 0.f, a2 = 0.f;
#pragma unroll 1
    for (int e = tid; e < cnt; e += 256) {
        int n = s_list[e];
        int src = (n - lab + N_TBINS) & (N_TBINS - 1);
        float lam = s_scaled[src];
        float log_lam, aa, bb, inv_alpha, v_r;
        rej_params(lam, log_lam, aa, bb, inv_alpha, v_r);
        float kval = -1.0f;
        uint32_t jj = jbase + (uint32_t)n;
#pragma unroll 1
        for (int t = tstop - 1; t >= 0; t--) {
            float kc;
            if (rej_step(s_rs0[t], s_rs1[t], jj, lam, log_lam, aa, bb,
                         inv_alpha, v_r, false, kc)) {
                kval = kc;
                break;
            }
        }
        a0 = fmaf(kval, __ldg(&W[n]), a0);
        a1 = fmaf(kval, __ldg(&W[N_TBINS + n]), a1);
        a2 = fmaf(kval, __ldg(&W[2 * N_TBINS + n]), a2);
    }

#pragma unroll
    for (int off = 16; off > 0; off >>= 1) {
        a0 += __shfl_xor_sync(0xFFFFFFFFu, a0, off);
        a1 += __shfl_xor_sync(0xFFFFFFFFu, a1, off);
        a2 += __shfl_xor_sync(0xFFFFFFFFu, a2, off);
    }
    __shared__ float wsum[3][8];
    int wid = tid >> 5, lane = tid & 31;
    if (lane == 0) { wsum[0][wid] = a0; wsum[1][wid] = a1; wsum[2][wid] = a2; }
    __syncthreads();
    if (tid < 3) {
        float t = 0.f;
#pragma unroll
        for (int w = 0; w < 8; w++) t += wsum[tid][w];
        out[b * 3 + tid] = t + g_partial[b * 3 + tid];
    }
}

extern "C" void kernel_launch(void* const* d_in, const int* in_sizes, int n_in,
                              void* d_out, int out_size) {
    const float* ill    = (const float*)d_in[0];
    const float* W      = (const float*)d_in[1];
    const int*   labels = (const int*)d_in[2];
    const float* pc     = (const float*)d_in[3];
    const float* sbr    = (const float*)d_in[4];
    int B = in_sizes[2];
    if (B > MAXB) B = MAXB;

    chains_kernel<<<1, 256>>>();
    setup_kernel<<<1, 256>>>(ill, pc, sbr);
    main_kernel<<<B, 256>>>(W, labels);
    finish_kernel<<<B, 256>>>(W, labels, (float*)d_out);
}

// round 12
// speedup vs baseline: 1.5114x; 1.0708x over previous
#include <cuda_runtime.h>
#include <stdint.h>

#define N_TBINS 1024
#define TK 96
#define TR 48
#define TT_LO 9000
#define TT_N  2001
#define MAXB  32768

__device__ float g_scaled[N_TBINS];
__device__ uint2 g_ksub[TK];
__device__ uint2 g_rs0[TR];
__device__ uint2 g_rs1[TR];
__device__ int   g_tstop;
__device__ float g_lamfake = 10000.0f;  // opaque to the compiler
__device__ float g_tt[TT_N];
__device__ float g_partial[MAXB * 3];
__device__ int   g_rejcnt;
__device__ int   g_rejsrc[N_TBINS];
__device__ float g_rejlam[N_TBINS];

__device__ __forceinline__ uint32_t rotl32(uint32_t x, int r) {
    return __funnelshift_l(x, x, r);
}

__device__ __forceinline__ uint2 threefry2x32(uint2 key, uint32_t x0, uint32_t x1) {
    uint32_t ks0 = key.x, ks1 = key.y;
    uint32_t ks2 = ks0 ^ ks1 ^ 0x1BD11BDAu;
    x0 += ks0; x1 += ks1;
#define TF_R(r) { x0 += x1; x1 = rotl32(x1, r); x1 ^= x0; }
    TF_R(13) TF_R(15) TF_R(26) TF_R(6)
    x0 += ks1; x1 += ks2 + 1u;
    TF_R(17) TF_R(29) TF_R(16) TF_R(24)
    x0 += ks2; x1 += ks0 + 2u;
    TF_R(13) TF_R(15) TF_R(26) TF_R(6)
    x0 += ks0; x1 += ks1 + 3u;
    TF_R(17) TF_R(29) TF_R(16) TF_R(24)
    x0 += ks1; x1 += ks2 + 4u;
    TF_R(13) TF_R(15) TF_R(26) TF_R(6)
    x0 += ks2; x1 += ks0 + 5u;
#undef TF_R
    return make_uint2(x0, x1);
}

__device__ __forceinline__ float u01(uint2 key, uint32_t j) {
    uint2 r = threefry2x32(key, 0u, j);
    uint32_t bits = r.x ^ r.y;
    return __uint_as_float((bits >> 9) | 0x3f800000u) - 1.0f;
}

// XLA Lanczos lgamma (g=7), x >= 1 here.
__device__ __forceinline__ float lgamma_xla(float x) {
    float z = __fsub_rn(x, 1.0f);
    float sum = 0.99999999999980993f;
    const float lanc[8] = {
        676.520368121885098567009190444019f,
        -1259.13921672240287047156078755283f,
        771.3234287776530788486528258894f,
        -176.61502916214059906584551354f,
        12.507343278686904814458936853f,
        -0.13857109526572011689554707f,
        9.984369578019570859563e-6f,
        1.50563273514931155834e-7f};
#pragma unroll
    for (int i = 0; i < 8; i++) {
        float denom = __fadd_rn(__fadd_rn(z, (float)i), 1.0f);
        sum = __fadd_rn(sum, __fdiv_rn(lanc[i], denom));
    }
    float t = __fadd_rn(7.5f, z);
    float log_t = __fadd_rn(2.0149030205422647f, log1pf(__fdiv_rn(z, 7.5f)));
    float v = __fmul_rn(__fsub_rn(__fadd_rn(z, 0.5f), __fdiv_rn(t, log_t)), log_t);
    return __fadd_rn(__fadd_rn(0.9189385332046727f, v), logf(sum));
}

// One Hormann rejection iteration; use_table => fake-lambda tt lookup.
__device__ __forceinline__ bool rej_step(uint2 s0, uint2 s1, uint32_t j,
                                         float lam, float log_lam, float aa,
                                         float bb, float inv_alpha, float v_r,
                                         bool use_table, float& kc_out) {
    float u = __fsub_rn(u01(s0, j), 0.5f);
    float v = u01(s1, j);
    float us = __fsub_rn(0.5f, fabsf(u));
    float kc = floorf(__fadd_rn(
        __fadd_rn(__fmul_rn(__fadd_rn(__fdiv_rn(__fadd_rn(aa, aa), us), bb), u), lam),
        0.43f));
    kc_out = kc;
    bool accept1 = (us >= 0.07f) && (v <= v_r);
    if (accept1) return true;
    bool reject = (kc < 0.0f) || ((us < 0.013f) && (v > us));
    if (reject) return false;
    float s = logf(__fdiv_rn(__fmul_rn(v, inv_alpha),
                             __fadd_rn(__fdiv_rn(aa, __fmul_rn(us, us)), bb)));
    float tt;
    if (use_table && kc >= (float)TT_LO && kc <= (float)(TT_LO + TT_N - 1)) {
        tt = __ldg(&g_tt[(int)kc - TT_LO]);
    } else {
        tt = __fsub_rn(__fadd_rn(-lam, __fmul_rn(kc, log_lam)),
                       lgamma_xla(__fadd_rn(kc, 1.0f)));
    }
    return s <= tt;
}

__device__ __forceinline__ void rej_params(float lam, float& log_lam, float& aa,
                                           float& bb, float& inv_alpha, float& v_r) {
    log_lam = logf(lam);
    bb = __fadd_rn(0.931f, __fmul_rn(2.53f, sqrtf(lam)));
    aa = __fadd_rn(-0.059f, __fmul_rn(0.02483f, bb));
    inv_alpha = __fadd_rn(1.1239f, __fdiv_rn(1.1328f, __fsub_rn(bb, 3.4f)));
    v_r = __fsub_rn(0.9277f, __fdiv_rn(3.6224f, __fsub_rn(bb, 2.0f)));
}

// chains + tt table + counters reset.
__global__ void __launch_bounds__(256, 1)
chains_kernel() {
    int tid = threadIdx.x;
    if (tid == 0) {
        g_tstop = 0;
        g_rejcnt = 0;
        uint2 key0 = make_uint2(0u, 42u);
        uint2 r = key0;
#pragma unroll 1
        for (int t = 0; t < TK; t++) {
            g_ksub[t] = threefry2x32(r, 0u, 1u);
            r = threefry2x32(r, 0u, 0u);
        }
        uint2 c = key0;
#pragma unroll 1
        for (int t = 0; t < TR; t++) {
            g_rs0[t] = threefry2x32(c, 0u, 1u);
            g_rs1[t] = threefry2x32(c, 0u, 2u);
            c = threefry2x32(c, 0u, 0u);
        }
    }
    float lamf = g_lamfake;
    float log_lam = logf(lamf);
#pragma unroll 1
    for (int m = tid; m < TT_N; m += 256) {
        float kc = (float)(TT_LO + m);
        g_tt[m] = __fsub_rn(__fadd_rn(-lamf, __fmul_rn(kc, log_lam)),
                            lgamma_xla(__fadd_rn(kc, 1.0f)));
    }
}

// setup: scaled rates + rejection src/lam list (row-independent).
__global__ void __launch_bounds__(256, 1)
setup_kernel(const float* __restrict__ ill,
             const float* __restrict__ pc,
             const float* __restrict__ sbr) {
    __shared__ float s[256];
    int tid = threadIdx.x;
    float acc = 0.0f;
#pragma unroll
    for (int i = 0; i < 4; i++) acc = __fadd_rn(acc, ill[tid + i * 256]);
    s[tid] = acc;
    __syncthreads();
    for (int st = 128; st > 0; st >>= 1) {
        if (tid < st) s[tid] = __fadd_rn(s[tid], s[tid + st]);
        __syncthreads();
    }
    float area = s[0];
    float scaling = __fdiv_rn(pc[0], area);
    float amb = __fdiv_rn(__fdiv_rn(pc[0], sbr[0]), 1024.0f);
#pragma unroll
    for (int i = 0; i < 4; i++) {
        int n = tid + i * 256;
        float v = fmaxf(__fadd_rn(__fmul_rn(ill[n], scaling), amb), 0.0f);
        g_scaled[n] = v;
        if (!(v < 10.0f)) {
            int e = atomicAdd(&g_rejcnt, 1);
            g_rejsrc[e] = n;
            g_rejlam[e] = v;
        }
    }
}

// Kernel A (unchanged from passing R11): scan -> tstop; Knuth; partial GEMM.
__global__ void __launch_bounds__(256)
main_kernel(const float* __restrict__ W, const int* __restrict__ labels) {
    __shared__ float s_scaled[N_TBINS];
    __shared__ float s_k[N_TBINS];
    __shared__ uint2 s_ksub[TK];
    __shared__ uint2 s_rs0[TR];
    __shared__ uint2 s_rs1[TR];
    __shared__ float s_fake[6];
    __shared__ int s_cur[8];
    __shared__ int s_cur2[8];

    int tid = threadIdx.x;
    int b = blockIdx.x;
    int wid = tid >> 5, lane = tid & 31;

    for (int i = tid; i < N_TBINS; i += 256) s_scaled[i] = g_scaled[i];
    if (tid < TK) s_ksub[tid] = g_ksub[tid];
    if (tid < TR) { s_rs0[tid] = g_rs0[tid]; s_rs1[tid] = g_rs1[tid]; }
    if (tid < 8) { s_cur[tid] = 32; s_cur2[tid] = 32; }
    if (tid == 0) {
        float lamf = g_lamfake;
        float ll, aa, bb, ia, vr;
        rej_params(lamf, ll, aa, bb, ia, vr);
        s_fake[0] = lamf; s_fake[1] = ll; s_fake[2] = aa;
        s_fake[3] = bb;   s_fake[4] = ia; s_fake[5] = vr;
    }
    __syncthreads();

    int lab = labels[b];
    uint32_t jbase = (uint32_t)b * N_TBINS;

    // ---- phase 0: first-accept scan, work-stealing over warp's 128 bins ----
    {
        int tmax = 0;
        float lam, log_lam, aa, bb, inv_alpha, v_r;
        bool use_table = true;
        uint32_t j = 0;
        int t = 0;
        bool active = true;
        {
            int n = wid * 128 + lane;
            int src = (n - lab + N_TBINS) & (N_TBINS - 1);
            float l0 = s_scaled[src];
            if (l0 < 10.0f) {
                lam = s_fake[0]; log_lam = s_fake[1]; aa = s_fake[2];
                bb = s_fake[3]; inv_alpha = s_fake[4]; v_r = s_fake[5];
                use_table = true;
            } else {
                lam = l0; rej_params(lam, log_lam, aa, bb, inv_alpha, v_r);
                use_table = false;
            }
            j = jbase + (uint32_t)n; t = 0;
        }
#pragma unroll 1
        while (__ballot_sync(0xFFFFFFFFu, active)) {
            if (active) {
                float kc;
                bool acc = rej_step(s_rs0[t], s_rs1[t], j, lam, log_lam, aa, bb,
                                    inv_alpha, v_r, use_table, kc);
                t++;
                if (acc || t >= TR) {
                    if (acc && t > tmax) tmax = t;
                    int r = atomicAdd(&s_cur[wid], 1);
                    if (r >= 128) {
                        active = false;
                    } else {
                        int n = wid * 128 + r;
                        int src = (n - lab + N_TBINS) & (N_TBINS - 1);
                        float l0 = s_scaled[src];
                        if (l0 < 10.0f) {
                            lam = s_fake[0]; log_lam = s_fake[1]; aa = s_fake[2];
                            bb = s_fake[3]; inv_alpha = s_fake[4]; v_r = s_fake[5];
                            use_table = true;
                        } else {
                            lam = l0; rej_params(lam, log_lam, aa, bb, inv_alpha, v_r);
                            use_table = false;
                        }
                        j = jbase + (uint32_t)n; t = 0;
                    }
                }
            }
        }
#pragma unroll
        for (int off = 16; off > 0; off >>= 1)
            tmax = max(tmax, __shfl_xor_sync(0xFFFFFFFFu, tmax, off));
        if (lane == 0) atomicMax(&g_tstop, tmax);
    }

    // ---- phase 1: work-stealing Knuth over lam<10 bins ----
    {
        float lp = 0.f, neg = 0.f;
        int k = 0, rel = -1;
        uint32_t j = 0;
        bool active = false;
        {
            int r = lane;
            while (true) {
                if (r >= 128) { active = false; break; }
                int n = wid * 128 + r;
                int src = (n - lab + N_TBINS) & (N_TBINS - 1);
                float l0 = s_scaled[src];
                if (l0 < 10.0f) {
                    neg = -l0; lp = 0.f; k = 0; j = jbase + (uint32_t)n;
                    rel = r; active = true; break;
                }
                s_k[n] = 0.0f;  // rejection bin: zero for partial GEMM
                r = atomicAdd(&s_cur2[wid], 1);
            }
        }
#pragma unroll 1
        while (__ballot_sync(0xFFFFFFFFu, active)) {
            if (active) {
                if (lp > neg && k < TK) {
                    lp = __fadd_rn(lp, logf(u01(s_ksub[k], j)));
                    k++;
                } else {
                    s_k[wid * 128 + rel] = (float)(k - 1);
                    int r = atomicAdd(&s_cur2[wid], 1);
                    while (true) {
                        if (r >= 128) { active = false; break; }
                        int n = wid * 128 + r;
                        int src = (n - lab + N_TBINS) & (N_TBINS - 1);
                        float l0 = s_scaled[src];
                        if (l0 < 10.0f) {
                            neg = -l0; lp = 0.f; k = 0; j = jbase + (uint32_t)n;
                            rel = r; break;
                        }
                        s_k[n] = 0.0f;
                        r = atomicAdd(&s_cur2[wid], 1);
                    }
                }
            }
        }
    }
    __syncthreads();

    // ---- phase 2: Knuth-only partial GEMM ----
    float a0 = 0.f, a1 = 0.f, a2 = 0.f;
#pragma unroll
    for (int i = 0; i < 4; i++) {
        int n = tid + i * 256;
        float kv = s_k[n];
        a0 = fmaf(kv, __ldg(&W[n]), a0);
        a1 = fmaf(kv, __ldg(&W[N_TBINS + n]), a1);
        a2 = fmaf(kv, __ldg(&W[2 * N_TBINS + n]), a2);
    }
#pragma unroll
    for (int off = 16; off > 0; off >>= 1) {
        a0 += __shfl_xor_sync(0xFFFFFFFFu, a0, off);
        a1 += __shfl_xor_sync(0xFFFFFFFFu, a1, off);
        a2 += __shfl_xor_sync(0xFFFFFFFFu, a2, off);
    }
    __shared__ float wsum[3][8];
    if (lane == 0) { wsum[0][wid] = a0; wsum[1][wid] = a1; wsum[2][wid] = a2; }
    __syncthreads();
    if (tid < 3) {
        float t = 0.f;
#pragma unroll
        for (int w = 0; w < 8; w++) t += wsum[tid][w];
        g_partial[b * 3 + tid] = t;
    }
}

// Kernel B: warp-per-row, precomputed rejection list, no 1024 sweep.
__global__ void __launch_bounds__(256)
finish_kernel(const float* __restrict__ W,
              const int* __restrict__ labels,
              float* __restrict__ out,
              int B) {
    __shared__ uint2 s_rs0[TR];
    __shared__ uint2 s_rs1[TR];
    __shared__ int s_src[N_TBINS];
    __shared__ float s_lam[N_TBINS];
    __shared__ int s_cnt;
    __shared__ int s_tstop;

    int tid = threadIdx.x;
    int wid = tid >> 5, lane = tid & 31;

    if (tid < TR) { s_rs0[tid] = g_rs0[tid]; s_rs1[tid] = g_rs1[tid]; }
    if (tid == 0) { s_cnt = g_rejcnt; s_tstop = g_tstop; }
    __syncthreads();
    int cnt = s_cnt;
    for (int i = tid; i < cnt; i += 256) {
        s_src[i] = g_rejsrc[i];
        s_lam[i] = g_rejlam[i];
    }
    __syncthreads();

    int row = blockIdx.x * 8 + wid;
    if (row >= B) return;
    int lab = labels[row];
    uint32_t jbase = (uint32_t)row * N_TBINS;
    int tstop = s_tstop;

    float a0 = 0.f, a1 = 0.f, a2 = 0.f;
#pragma unroll 1
    for (int e = lane; e < cnt; e += 32) {
        float lam = s_lam[e];
        float log_lam, aa, bb, inv_alpha, v_r;
        rej_params(lam, log_lam, aa, bb, inv_alpha, v_r);
        int n = (s_src[e] + lab) & (N_TBINS - 1);
        uint32_t jj = jbase + (uint32_t)n;
        float kval = -1.0f;
#pragma unroll 1
        for (int t = tstop - 1; t >= 0; t--) {
            float kc;
            if (rej_step(s_rs0[t], s_rs1[t], jj, lam, log_lam, aa, bb,
                         inv_alpha, v_r, false, kc)) {
                kval = kc;
                break;
            }
        }
        a0 = fmaf(kval, __ldg(&W[n]), a0);
        a1 = fmaf(kval, __ldg(&W[N_TBINS + n]), a1);
        a2 = fmaf(kval, __ldg(&W[2 * N_TBINS + n]), a2);
    }

#pragma unroll
    for (int off = 16; off > 0; off >>= 1) {
        a0 += __shfl_xor_sync(0xFFFFFFFFu, a0, off);
        a1 += __shfl_xor_sync(0xFFFFFFFFu, a1, off);
        a2 += __shfl_xor_sync(0xFFFFFFFFu, a2, off);
    }
    if (lane == 0) {
        out[row * 3 + 0] = a0 + g_partial[row * 3 + 0];
        out[row * 3 + 1] = a1 + g_partial[row * 3 + 1];
        out[row * 3 + 2] = a2 + g_partial[row * 3 + 2];
    }
}

extern "C" void kernel_launch(void* const* d_in, const int* in_sizes, int n_in,
                              void* d_out, int out_size) {
    const float* ill    = (const float*)d_in[0];
    const float* W      = (const float*)d_in[1];
    const int*   labels = (const int*)d_in[2];
    const float* pc     = (const float*)d_in[3];
    const float* sbr    = (const float*)d_in[4];
    int B = in_sizes[2];
    if (B > MAXB) B = MAXB;

    chains_kernel<<<1, 256>>>();
    setup_kernel<<<1, 256>>>(ill, pc, sbr);
    main_kernel<<<B, 256>>>(W, labels);
    finish_kernel<<<(B + 7) / 8, 256>>>(W, labels, (float*)d_out, B);
}